// round 14
// baseline (speedup 1.0000x reference)
#include <cuda_runtime.h>
#include <cuda_fp16.h>
#include <cstdint>
#include <mma.h>

using namespace nvcuda;

// ---------------- problem constants ----------------
#define BATCH 4
#define SEQ   2048
#define CH    1024
#define FF    2048
#define NHEAD 16
#define HDIM  64
#define MROWS (BATCH*SEQ)            // 8192
#define NELEM ((size_t)MROWS*CH)     // 8388608

// ---------------- scratch (no cudaMalloc allowed) ----------------
__device__ __half g_xh   [NELEM];
__device__ __half g_keysh[NELEM];
__device__ __half g_Wqh  [CH*CH];
__device__ __half g_Wkh  [CH*CH];
__device__ __half g_Wvh  [CH*CH];
__device__ __half g_Woh  [CH*CH];
__device__ __half g_fc1h [FF*CH];
__device__ __half g_fc2h [CH*FF];
__device__ __half g_Qh2  [NELEM];
__device__ __half g_Kh2  [NELEM];
__device__ __half g_Vh2  [NELEM];
__device__ __half g_attnh[NELEM];
__device__ __half g_inth [NELEM];
__device__ __half g_H1h  [(size_t)MROWS*FF];
__device__ float  g_O  [NELEM];
__device__ float  g_int[NELEM];
__device__ float  g_F  [NELEM];

__device__ __forceinline__ __half* scratch_h(int id) {
    switch (id) {
        case 1:  return g_xh;    case 2:  return g_keysh;
        case 3:  return g_Wqh;   case 4:  return g_Wkh;
        case 5:  return g_Wvh;   case 6:  return g_Woh;
        case 7:  return g_fc1h;  case 8:  return g_fc2h;
        case 9:  return g_Qh2;   case 10: return g_Kh2;
        case 11: return g_Vh2;   case 12: return g_attnh;
        case 13: return g_inth;  case 14: return g_H1h;
    }
    return nullptr;
}
__device__ __forceinline__ float* scratch_f(int id) {
    switch (id) {
        case 1: return g_O;  case 2: return g_int; case 3: return g_F;
    }
    return nullptr;
}

// ---------------- cp.async helpers ----------------
__device__ __forceinline__ void cp16(void* smem_dst, const void* gsrc) {
    unsigned int s = (unsigned int)__cvta_generic_to_shared(smem_dst);
    asm volatile("cp.async.cg.shared.global [%0], [%1], 16;" :: "r"(s), "l"(gsrc));
}
__device__ __forceinline__ void cp_commit() {
    asm volatile("cp.async.commit_group;");
}
template<int N>
__device__ __forceinline__ void cp_wait() {
    asm volatile("cp.async.wait_group %0;" :: "n"(N));
}

// =====================================================================
// conv8: fp32 -> fp16 for x, keys and the six weight matrices.
// =====================================================================
__global__ __launch_bounds__(256)
void conv8(const float* __restrict__ x, const float* __restrict__ keys,
           const float* __restrict__ wq, const float* __restrict__ wk,
           const float* __restrict__ wv, const float* __restrict__ wo,
           const float* __restrict__ f1, const float* __restrict__ f2)
{
    const size_t T = 6291456;   // total float4 chunks
    for (size_t i = (size_t)blockIdx.x*blockDim.x + threadIdx.x; i < T;
         i += (size_t)gridDim.x*blockDim.x) {
        const float* src; __half* dst; size_t off;
        if      (i < 2097152) { src=x;    dst=g_xh;    off=i; }
        else if (i < 4194304) { src=keys; dst=g_keysh; off=i-2097152; }
        else if (i < 4456448) { src=wq;   dst=g_Wqh;   off=i-4194304; }
        else if (i < 4718592) { src=wk;   dst=g_Wkh;   off=i-4456448; }
        else if (i < 4980736) { src=wv;   dst=g_Wvh;   off=i-4718592; }
        else if (i < 5242880) { src=wo;   dst=g_Woh;   off=i-4980736; }
        else if (i < 5767168) { src=f1;   dst=g_fc1h;  off=i-5242880; }
        else                  { src=f2;   dst=g_fc2h;  off=i-5767168; }
        float4 v = ((const float4*)src)[off];
        __half2* d2 = (__half2*)dst;
        d2[off*2]   = __floats2half2_rn(v.x, v.y);
        d2[off*2+1] = __floats2half2_rn(v.z, v.w);
    }
}

// =====================================================================
// GEMM fp16 v5: C = A @ B^T (+bias,+silu)
// block tile 128x64, BK=64, 256 threads = 8 warps (4x2), warp 32x32.
// __launch_bounds__(256,3): <=85 regs -> 3 CTAs/SM (24 warps).
// Double-buffered cp.async, 1 barrier/stage.
// =====================================================================
#define GLDH 72
template<int EPI, int OUTH>   // EPI 0:none 1:+bias 2:+bias+silu
__global__ __launch_bounds__(256, 3)
void gemm_h(int aid, int bid, const float* __restrict__ bias,
            int cid, int M, int N, int K)
{
    const __half* A = scratch_h(aid);
    const __half* B = scratch_h(bid);

    extern __shared__ __half smh[];
    __half* As[2] = { smh,         smh + 9216  };   // 128 x 72 each
    __half* Bs[2] = { smh + 18432, smh + 23040 };   // 64 x 72 each
    float* Cs = (float*)smh;                        // epilogue: 128x68 fp32 (34816 B < 55296 B)

    const int m0 = blockIdx.y << 7;      // 128-row tile
    const int n0 = blockIdx.x << 6;      // 64-col tile
    const int tid  = threadIdx.x;
    const int warp = tid >> 5;
    const int wr = warp >> 1;            // 0..3 -> 32-row strip
    const int wc = warp & 1;             // 0..1 -> 32-col strip

    wmma::fragment<wmma::accumulator,16,16,16,float> c[2][2];
    #pragma unroll
    for (int i=0;i<2;i++)
        #pragma unroll
        for (int j=0;j<2;j++) wmma::fill_fragment(c[i][j], 0.f);

    const int NS = K >> 6;               // BK=64 stages

    // prologue: stage 0  (A: 128 rows = 1024 chunks (4/thr); B: 64 rows = 512 chunks (2/thr))
    #pragma unroll
    for (int i=0;i<4;i++) {
        int cch = tid + (i<<8);
        int r = cch >> 3, col = (cch & 7) << 3;
        cp16(&As[0][r*GLDH + col], &A[(size_t)(m0+r)*K + col]);
    }
    #pragma unroll
    for (int i=0;i<2;i++) {
        int cch = tid + (i<<8);
        int r = cch >> 3, col = (cch & 7) << 3;
        cp16(&Bs[0][r*GLDH + col], &B[(size_t)(n0+r)*K + col]);
    }
    cp_commit();

    for (int s=0; s<NS; s++) {
        const int buf = s & 1;
        cp_wait<0>();
        __syncthreads();
        if (s+1 < NS) {
            const int k0 = (s+1) << 6;
            #pragma unroll
            for (int i=0;i<4;i++) {
                int cch = tid + (i<<8);
                int r = cch >> 3, col = (cch & 7) << 3;
                cp16(&As[buf^1][r*GLDH + col], &A[(size_t)(m0+r)*K + k0 + col]);
            }
            #pragma unroll
            for (int i=0;i<2;i++) {
                int cch = tid + (i<<8);
                int r = cch >> 3, col = (cch & 7) << 3;
                cp16(&Bs[buf^1][r*GLDH + col], &B[(size_t)(n0+r)*K + k0 + col]);
            }
            cp_commit();
        }

        #pragma unroll
        for (int kk=0; kk<64; kk+=16) {
            wmma::fragment<wmma::matrix_a,16,16,16,__half,wmma::row_major> a[2];
            wmma::fragment<wmma::matrix_b,16,16,16,__half,wmma::col_major> bf[2];
            #pragma unroll
            for (int i=0;i<2;i++)
                wmma::load_matrix_sync(a[i], &As[buf][(wr*32+i*16)*GLDH + kk], GLDH);
            #pragma unroll
            for (int j=0;j<2;j++)
                wmma::load_matrix_sync(bf[j], &Bs[buf][(wc*32+j*16)*GLDH + kk], GLDH);
            #pragma unroll
            for (int i=0;i<2;i++)
                #pragma unroll
                for (int j=0;j<2;j++)
                    wmma::mma_sync(c[i][j], a[i], bf[j], c[i][j]);
        }
    }

    // epilogue: park to fp32 smem (128x68), one linear pass
    __syncthreads();
    #pragma unroll
    for (int i=0;i<2;i++)
        #pragma unroll
        for (int j=0;j<2;j++)
            wmma::store_matrix_sync(&Cs[(wr*32+i*16)*68 + wc*32 + j*16],
                                    c[i][j], 68, wmma::mem_row_major);
    __syncthreads();
    #pragma unroll
    for (int t=0;t<32;t++) {
        int idx = tid + (t<<8);              // 0..8191
        int r = idx >> 6, cc = idx & 63;
        float v = Cs[r*68 + cc];
        if (EPI >= 1) v += bias[n0 + cc];
        if (EPI == 2) v = v / (1.f + __expf(-v));
        size_t gpos = (size_t)(m0+r)*N + n0 + cc;
        if (OUTH) scratch_h(cid)[gpos] = __float2half_rn(v);
        else      scratch_f(cid)[gpos] = v;
    }
}

// =====================================================================
// Flash attention fp16 v2 (unchanged from R13, measured fast):
// Q tile 128, KV tiles 64, double-buffered cp.async, warp tile 32x32.
// QK fp16 mma -> fp32 S frags; exp on regs -> half accum frag -> sP;
// PV fp16 mma. Two barriers per KV tile. fp16 in/out. smem 74.2 KB.
// =====================================================================
#define PLDH 72
__global__ __launch_bounds__(256)
void attn_kernel()
{
    extern __shared__ __half smh[];
    __half* sQ = smh;                                   // 128x72
    __half* sK[2] = { smh + 9216,  smh + 13824 };       // 64x72 each
    __half* sV[2] = { smh + 18432, smh + 23040 };       // 64x72 each
    __half* sP = smh + 27648;                           // 128x72
    float*  sL = (float*)(smh + 36864);                 // 128 floats
    float*  sO = (float*)(smh + 9216);                  // 128x68 fp32, reuse sK/sV at end

    const int bh = blockIdx.y;
    const int b  = bh >> 4, h = bh & 15;
    const int q0 = blockIdx.x << 7;
    const __half* Qh = g_Qh2 + (size_t)b*SEQ*CH + h*HDIM;
    const __half* Kh = g_Kh2 + (size_t)b*SEQ*CH + h*HDIM;
    const __half* Vh = g_Vh2 + (size_t)b*SEQ*CH + h*HDIM;

    const int tid  = threadIdx.x;
    const int warp = tid >> 5;
    const int wr   = warp >> 1;          // 0..3 (32-row strip)
    const int wc   = warp & 1;           // 0..1 (32-col strip)
    const int myrow = tid >> 1;          // 0..127
    const int cb    = (tid & 1) << 5;    // 32-col chunk

    // Q tile: 128 rows x 64 halfs = 1024 16B chunks, 4/thread
    #pragma unroll
    for (int i=0;i<4;i++) {
        int cch = tid + (i<<8);
        int r = cch >> 3, col = (cch & 7) << 3;
        *(uint4*)&sQ[r*PLDH + col] = *(const uint4*)&Qh[(size_t)(q0+r)*CH + col];
    }

    wmma::fragment<wmma::accumulator,16,16,16,float> o[2][2];
    #pragma unroll
    for (int i=0;i<2;i++)
        #pragma unroll
        for (int j=0;j<2;j++) wmma::fill_fragment(o[i][j], 0.f);
    float l = 0.f;

    // prologue: KV stage 0 (64x64 halfs = 512 chunks each, 2/thread)
    #pragma unroll
    for (int i=0;i<2;i++) {
        int cch = tid + (i<<8);
        int r = cch >> 3, col = (cch & 7) << 3;
        cp16(&sK[0][r*PLDH + col], &Kh[(size_t)r*CH + col]);
        cp16(&sV[0][r*PLDH + col], &Vh[(size_t)r*CH + col]);
    }
    cp_commit();

    const int NT = SEQ / 64;
    for (int it=0; it<NT; it++) {
        const int buf = it & 1;
        cp_wait<0>();
        __syncthreads();                 // KV(buf) ready; buf^1, sP free
        if (it+1 < NT) {
            const int kt = (it+1) << 6;
            #pragma unroll
            for (int i=0;i<2;i++) {
                int cch = tid + (i<<8);
                int r = cch >> 3, col = (cch & 7) << 3;
                cp16(&sK[buf^1][r*PLDH + col], &Kh[(size_t)(kt+r)*CH + col]);
                cp16(&sV[buf^1][r*PLDH + col], &Vh[(size_t)(kt+r)*CH + col]);
            }
            cp_commit();
        }

        // ---- S(128x64) = Q @ K^T : fp32 accum frags ----
        wmma::fragment<wmma::accumulator,16,16,16,float> s[2][2];
        #pragma unroll
        for (int i=0;i<2;i++)
            #pragma unroll
            for (int j=0;j<2;j++) wmma::fill_fragment(s[i][j], 0.f);
        #pragma unroll
        for (int kk=0; kk<64; kk+=16) {
            wmma::fragment<wmma::matrix_a,16,16,16,__half,wmma::row_major> a[2];
            wmma::fragment<wmma::matrix_b,16,16,16,__half,wmma::col_major> bf[2];
            #pragma unroll
            for (int i=0;i<2;i++)
                wmma::load_matrix_sync(a[i], &sQ[(wr*32+i*16)*PLDH + kk], PLDH);
            #pragma unroll
            for (int j=0;j<2;j++)
                wmma::load_matrix_sync(bf[j], &sK[buf][(wc*32+j*16)*PLDH + kk], PLDH);
            #pragma unroll
            for (int i=0;i<2;i++)
                #pragma unroll
                for (int j=0;j<2;j++)
                    wmma::mma_sync(s[i][j], a[i], bf[j], s[i][j]);
        }

        // ---- P = exp(S*scale) on regs -> half accum frag -> sP ----
        #pragma unroll
        for (int i=0;i<2;i++)
            #pragma unroll
            for (int j=0;j<2;j++) {
                wmma::fragment<wmma::accumulator,16,16,16,__half> hp;
                #pragma unroll
                for (int t=0;t<hp.num_elements;t++)
                    hp.x[t] = __float2half_rn(__expf(s[i][j].x[t] * 0.125f));
                wmma::store_matrix_sync(&sP[(wr*32+i*16)*PLDH + wc*32 + j*16], hp,
                                        PLDH, wmma::mem_row_major);
            }
        __syncthreads();                 // P visible

        // ---- per-thread partial row sum from sP ----
        {
            const __half* bp = &sP[myrow*PLDH + cb];
            #pragma unroll
            for (int t=0;t<16;t++) {
                float2 p2 = __half22float2(*(const __half2*)&bp[t*2]);
                l += p2.x + p2.y;
            }
        }

        // ---- O(128x64) += P(128x64) @ V(64x64) ----
        #pragma unroll
        for (int kk=0; kk<64; kk+=16) {
            wmma::fragment<wmma::matrix_a,16,16,16,__half,wmma::row_major> pa[2];
            wmma::fragment<wmma::matrix_b,16,16,16,__half,wmma::row_major> vb[2];
            #pragma unroll
            for (int i=0;i<2;i++)
                wmma::load_matrix_sync(pa[i], &sP[(wr*32+i*16)*PLDH + kk], PLDH);
            #pragma unroll
            for (int j=0;j<2;j++)
                wmma::load_matrix_sync(vb[j], &sV[buf][kk*PLDH + wc*32 + j*16], PLDH);
            #pragma unroll
            for (int i=0;i<2;i++)
                #pragma unroll
                for (int j=0;j<2;j++)
                    wmma::mma_sync(o[i][j], pa[i], vb[j], o[i][j]);
        }
    }

    l += __shfl_xor_sync(0xffffffffu, l, 1);
    if ((tid & 1) == 0) sL[myrow] = 1.f / l;
    __syncthreads();                     // all PV done; sK/sV region free

    #pragma unroll
    for (int i=0;i<2;i++)
        #pragma unroll
        for (int j=0;j<2;j++)
            wmma::store_matrix_sync(&sO[(wr*32+i*16)*68 + wc*32 + j*16], o[i][j],
                                    68, wmma::mem_row_major);
    __syncthreads();

    #pragma unroll
    for (int t=0;t<32;t++) {
        int idx = tid + (t<<8);
        int r = idx >> 6, cc = idx & 63;
        g_attnh[(size_t)(b*SEQ + q0 + r)*CH + h*HDIM + cc] =
            __float2half_rn(sO[r*68+cc] * sL[r]);
    }
}

// =====================================================================
// Fused residual + LayerNorm (fp32), optional extra fp16 output copy.
// =====================================================================
__global__ __launch_bounds__(256)
void ln_kernel(int aidf, const float* __restrict__ Rext, int ridf,
               const float* __restrict__ g, const float* __restrict__ bb,
               float* __restrict__ Oext, int oidf, int oidh)
{
    const float* A = scratch_f(aidf);
    const float* R = Rext ? Rext : scratch_f(ridf);
    float* out = Oext ? Oext : scratch_f(oidf);
    __half* outh = (oidh > 0) ? scratch_h(oidh) : nullptr;

    __shared__ float s1[8], s2[8];
    const int row = blockIdx.x;
    const size_t base = (size_t)row * CH;
    const int tid = threadIdx.x;
    float v[4]; float sum = 0.f, sq = 0.f;
    #pragma unroll
    for (int i=0;i<4;i++) {
        int c = tid + (i<<8);
        float t = A[base+c] + R[base+c];
        v[i] = t; sum += t; sq += t*t;
    }
    #pragma unroll
    for (int o=16;o;o>>=1) {
        sum += __shfl_xor_sync(0xffffffffu, sum, o);
        sq  += __shfl_xor_sync(0xffffffffu, sq,  o);
    }
    if ((tid & 31) == 0) { s1[tid>>5] = sum; s2[tid>>5] = sq; }
    __syncthreads();
    if (tid < 32) {
        float a = (tid < 8) ? s1[tid] : 0.f;
        float b2 = (tid < 8) ? s2[tid] : 0.f;
        #pragma unroll
        for (int o=4;o;o>>=1) {
            a  += __shfl_xor_sync(0xffffffffu, a,  o);
            b2 += __shfl_xor_sync(0xffffffffu, b2, o);
        }
        if (tid == 0) { s1[0] = a; s2[0] = b2; }
    }
    __syncthreads();
    float mean = s1[0] * (1.f/CH);
    float var  = s2[0] * (1.f/CH) - mean*mean;
    float rstd = rsqrtf(var + 1e-5f);
    #pragma unroll
    for (int i=0;i<4;i++) {
        int c = tid + (i<<8);
        float r = (v[i] - mean) * rstd * g[c] + bb[c];
        out[base+c] = r;
        if (outh) outh[base+c] = __float2half_rn(r);
    }
}

// =====================================================================
extern "C" void kernel_launch(void* const* d_in, const int* in_sizes, int n_in,
                              void* d_out, int out_size)
{
    const float *x, *keys, *Wq, *Wk, *Wv, *Wo, *ln1_g, *ln1_b;
    const float *fc1_w, *fc1_b, *fc2_w, *fc2_b, *ln2_g, *ln2_b;

    if (in_sizes[0] == MROWS*CH) {
        x     = (const float*)d_in[0];
        keys  = (const float*)d_in[1];
        Wq    = (const float*)d_in[2];
        Wk    = (const float*)d_in[3];
        Wv    = (const float*)d_in[4];
        Wo    = (const float*)d_in[5];
        ln1_g = (const float*)d_in[6];
        ln1_b = (const float*)d_in[7];
        fc1_w = (const float*)d_in[8];
        fc1_b = (const float*)d_in[9];
        fc2_w = (const float*)d_in[10];
        fc2_b = (const float*)d_in[11];
        ln2_g = (const float*)d_in[12];
        ln2_b = (const float*)d_in[13];
    } else {
        Wk    = (const float*)d_in[0];
        Wo    = (const float*)d_in[1];
        Wq    = (const float*)d_in[2];
        Wv    = (const float*)d_in[3];
        fc1_b = (const float*)d_in[4];
        fc1_w = (const float*)d_in[5];
        fc2_b = (const float*)d_in[6];
        fc2_w = (const float*)d_in[7];
        keys  = (const float*)d_in[8];
        ln1_b = (const float*)d_in[9];
        ln1_g = (const float*)d_in[10];
        ln2_b = (const float*)d_in[11];
        ln2_g = (const float*)d_in[12];
        x     = (const float*)d_in[13];
    }
    float* out = (float*)d_out;

    const int GEMM_SMEM = 27648 * (int)sizeof(__half);           // 55296 B
    const int ATTN_SMEM = 36864 * (int)sizeof(__half) + 512;     // 74240 B
    cudaFuncSetAttribute(gemm_h<0,1>, cudaFuncAttributeMaxDynamicSharedMemorySize, GEMM_SMEM);
    cudaFuncSetAttribute(gemm_h<0,0>, cudaFuncAttributeMaxDynamicSharedMemorySize, GEMM_SMEM);
    cudaFuncSetAttribute(gemm_h<2,1>, cudaFuncAttributeMaxDynamicSharedMemorySize, GEMM_SMEM);
    cudaFuncSetAttribute(gemm_h<1,0>, cudaFuncAttributeMaxDynamicSharedMemorySize, GEMM_SMEM);
    cudaFuncSetAttribute(attn_kernel, cudaFuncAttributeMaxDynamicSharedMemorySize, ATTN_SMEM);

    dim3 blk(256);
    dim3 g1024(CH/64, MROWS/128);     // (16, 64)
    dim3 g2048(FF/64, MROWS/128);     // (32, 64)

    // 0) fp32 -> fp16 conversion of inputs + weights
    conv8<<<2048, blk>>>(x, keys, Wq, Wk, Wv, Wo, fc1_w, fc2_w);

    // 1) QKV projections (fp16 in, fp16 out)
    gemm_h<0,1><<<g1024, blk, GEMM_SMEM>>>(1, 3, nullptr, 9,  MROWS, CH, CH);  // Qh2
    gemm_h<0,1><<<g1024, blk, GEMM_SMEM>>>(2, 4, nullptr, 10, MROWS, CH, CH);  // Kh2
    gemm_h<0,1><<<g1024, blk, GEMM_SMEM>>>(2, 5, nullptr, 11, MROWS, CH, CH);  // Vh2

    // 2) attention: fp16 Q/K/V -> fp16 attnh
    dim3 ga(SEQ/128, BATCH*NHEAD);
    attn_kernel<<<ga, blk, ATTN_SMEM>>>();

    // 3) output projection + residual LN
    gemm_h<0,0><<<g1024, blk, GEMM_SMEM>>>(12, 6, nullptr, 1, MROWS, CH, CH);  // g_O
    ln_kernel<<<MROWS, blk>>>(1, x, 0, ln1_g, ln1_b, nullptr, 2, 13);          // g_int + g_inth

    // 4) MLP
    gemm_h<2,1><<<g2048, blk, GEMM_SMEM>>>(13, 7, fc1_b, 14, MROWS, FF, CH);   // H1h
    gemm_h<1,0><<<g1024, blk, GEMM_SMEM>>>(14, 8, fc2_b, 3,  MROWS, CH, FF);   // g_F
    ln_kernel<<<MROWS, blk>>>(3, nullptr, 2, ln2_g, ln2_b, out, 0, 0);
}

// round 15
// speedup vs baseline: 1.0144x; 1.0144x over previous
#include <cuda_runtime.h>
#include <cuda_fp16.h>
#include <cstdint>
#include <mma.h>

using namespace nvcuda;

// ---------------- problem constants ----------------
#define BATCH 4
#define SEQ   2048
#define CH    1024
#define FF    2048
#define NHEAD 16
#define HDIM  64
#define MROWS (BATCH*SEQ)            // 8192
#define NELEM ((size_t)MROWS*CH)     // 8388608

// ---------------- scratch (no cudaMalloc allowed) ----------------
__device__ __half g_xh   [NELEM];
__device__ __half g_keysh[NELEM];
__device__ __half g_Wqh  [CH*CH];
__device__ __half g_Wkh  [CH*CH];
__device__ __half g_Wvh  [CH*CH];
__device__ __half g_Woh  [CH*CH];
__device__ __half g_fc1h [FF*CH];
__device__ __half g_fc2h [CH*FF];
__device__ __half g_Qh2  [NELEM];
__device__ __half g_Kh2  [NELEM];
__device__ __half g_Vh2  [NELEM];
__device__ __half g_attnh[NELEM];
__device__ __half g_inth [NELEM];
__device__ __half g_H1h  [(size_t)MROWS*FF];
__device__ float  g_O  [NELEM];
__device__ float  g_int[NELEM];
__device__ float  g_F  [NELEM];

__device__ __forceinline__ __half* scratch_h(int id) {
    switch (id) {
        case 1:  return g_xh;    case 2:  return g_keysh;
        case 3:  return g_Wqh;   case 4:  return g_Wkh;
        case 5:  return g_Wvh;   case 6:  return g_Woh;
        case 7:  return g_fc1h;  case 8:  return g_fc2h;
        case 9:  return g_Qh2;   case 10: return g_Kh2;
        case 11: return g_Vh2;   case 12: return g_attnh;
        case 13: return g_inth;  case 14: return g_H1h;
    }
    return nullptr;
}
__device__ __forceinline__ float* scratch_f(int id) {
    switch (id) {
        case 1: return g_O;  case 2: return g_int; case 3: return g_F;
    }
    return nullptr;
}

// ---------------- cp.async helpers ----------------
__device__ __forceinline__ void cp16(void* smem_dst, const void* gsrc) {
    unsigned int s = (unsigned int)__cvta_generic_to_shared(smem_dst);
    asm volatile("cp.async.cg.shared.global [%0], [%1], 16;" :: "r"(s), "l"(gsrc));
}
__device__ __forceinline__ void cp_commit() {
    asm volatile("cp.async.commit_group;");
}
template<int N>
__device__ __forceinline__ void cp_wait() {
    asm volatile("cp.async.wait_group %0;" :: "n"(N));
}

// =====================================================================
// conv8: fp32 -> fp16 for x, keys and the six weight matrices.
// =====================================================================
__global__ __launch_bounds__(256)
void conv8(const float* __restrict__ x, const float* __restrict__ keys,
           const float* __restrict__ wq, const float* __restrict__ wk,
           const float* __restrict__ wv, const float* __restrict__ wo,
           const float* __restrict__ f1, const float* __restrict__ f2)
{
    const size_t T = 6291456;   // total float4 chunks
    for (size_t i = (size_t)blockIdx.x*blockDim.x + threadIdx.x; i < T;
         i += (size_t)gridDim.x*blockDim.x) {
        const float* src; __half* dst; size_t off;
        if      (i < 2097152) { src=x;    dst=g_xh;    off=i; }
        else if (i < 4194304) { src=keys; dst=g_keysh; off=i-2097152; }
        else if (i < 4456448) { src=wq;   dst=g_Wqh;   off=i-4194304; }
        else if (i < 4718592) { src=wk;   dst=g_Wkh;   off=i-4456448; }
        else if (i < 4980736) { src=wv;   dst=g_Wvh;   off=i-4718592; }
        else if (i < 5242880) { src=wo;   dst=g_Woh;   off=i-4980736; }
        else if (i < 5767168) { src=f1;   dst=g_fc1h;  off=i-5242880; }
        else                  { src=f2;   dst=g_fc2h;  off=i-5767168; }
        float4 v = ((const float4*)src)[off];
        __half2* d2 = (__half2*)dst;
        d2[off*2]   = __floats2half2_rn(v.x, v.y);
        d2[off*2+1] = __floats2half2_rn(v.z, v.w);
    }
}

// =====================================================================
// GEMM fp16 v6: C = A @ B^T (+bias,+silu)
// block tile 128x64, BK=64, 256 threads = 8 warps (4x2), warp 32x32.
// __launch_bounds__(256,3): 3 CTAs/SM (24 warps).
// EPI=0: DIRECT fragment store to global (no smem epilogue, no barriers).
// EPI>0: smem epilogue with bias/silu.
// =====================================================================
#define GLDH 72
template<int EPI, int OUTH>   // EPI 0:none 1:+bias 2:+bias+silu
__global__ __launch_bounds__(256, 3)
void gemm_h(int aid, int bid, const float* __restrict__ bias,
            int cid, int M, int N, int K)
{
    const __half* A = scratch_h(aid);
    const __half* B = scratch_h(bid);

    extern __shared__ __half smh[];
    __half* As[2] = { smh,         smh + 9216  };   // 128 x 72 each
    __half* Bs[2] = { smh + 18432, smh + 23040 };   // 64 x 72 each
    float* Cs = (float*)smh;                        // epilogue: 128x68 fp32

    const int m0 = blockIdx.y << 7;      // 128-row tile
    const int n0 = blockIdx.x << 6;      // 64-col tile
    const int tid  = threadIdx.x;
    const int warp = tid >> 5;
    const int wr = warp >> 1;            // 0..3 -> 32-row strip
    const int wc = warp & 1;             // 0..1 -> 32-col strip

    wmma::fragment<wmma::accumulator,16,16,16,float> c[2][2];
    #pragma unroll
    for (int i=0;i<2;i++)
        #pragma unroll
        for (int j=0;j<2;j++) wmma::fill_fragment(c[i][j], 0.f);

    const int NS = K >> 6;               // BK=64 stages

    // prologue: stage 0
    #pragma unroll
    for (int i=0;i<4;i++) {
        int cch = tid + (i<<8);
        int r = cch >> 3, col = (cch & 7) << 3;
        cp16(&As[0][r*GLDH + col], &A[(size_t)(m0+r)*K + col]);
    }
    #pragma unroll
    for (int i=0;i<2;i++) {
        int cch = tid + (i<<8);
        int r = cch >> 3, col = (cch & 7) << 3;
        cp16(&Bs[0][r*GLDH + col], &B[(size_t)(n0+r)*K + col]);
    }
    cp_commit();

    for (int s=0; s<NS; s++) {
        const int buf = s & 1;
        cp_wait<0>();
        __syncthreads();
        if (s+1 < NS) {
            const int k0 = (s+1) << 6;
            #pragma unroll
            for (int i=0;i<4;i++) {
                int cch = tid + (i<<8);
                int r = cch >> 3, col = (cch & 7) << 3;
                cp16(&As[buf^1][r*GLDH + col], &A[(size_t)(m0+r)*K + k0 + col]);
            }
            #pragma unroll
            for (int i=0;i<2;i++) {
                int cch = tid + (i<<8);
                int r = cch >> 3, col = (cch & 7) << 3;
                cp16(&Bs[buf^1][r*GLDH + col], &B[(size_t)(n0+r)*K + k0 + col]);
            }
            cp_commit();
        }

        #pragma unroll
        for (int kk=0; kk<64; kk+=16) {
            wmma::fragment<wmma::matrix_a,16,16,16,__half,wmma::row_major> a[2];
            wmma::fragment<wmma::matrix_b,16,16,16,__half,wmma::col_major> bf[2];
            #pragma unroll
            for (int i=0;i<2;i++)
                wmma::load_matrix_sync(a[i], &As[buf][(wr*32+i*16)*GLDH + kk], GLDH);
            #pragma unroll
            for (int j=0;j<2;j++)
                wmma::load_matrix_sync(bf[j], &Bs[buf][(wc*32+j*16)*GLDH + kk], GLDH);
            #pragma unroll
            for (int i=0;i<2;i++)
                #pragma unroll
                for (int j=0;j<2;j++)
                    wmma::mma_sync(c[i][j], a[i], bf[j], c[i][j]);
        }
    }

    if (EPI == 0) {
        // direct store: no smem, no barriers
        if (OUTH) {
            __half* C = scratch_h(cid);
            #pragma unroll
            for (int i=0;i<2;i++)
                #pragma unroll
                for (int j=0;j<2;j++) {
                    wmma::fragment<wmma::accumulator,16,16,16,__half> hc;
                    #pragma unroll
                    for (int t=0;t<hc.num_elements;t++)
                        hc.x[t] = __float2half_rn(c[i][j].x[t]);
                    wmma::store_matrix_sync(
                        &C[(size_t)(m0+wr*32+i*16)*N + n0 + wc*32 + j*16],
                        hc, N, wmma::mem_row_major);
                }
        } else {
            float* C = scratch_f(cid);
            #pragma unroll
            for (int i=0;i<2;i++)
                #pragma unroll
                for (int j=0;j<2;j++)
                    wmma::store_matrix_sync(
                        &C[(size_t)(m0+wr*32+i*16)*N + n0 + wc*32 + j*16],
                        c[i][j], N, wmma::mem_row_major);
        }
    } else {
        // smem epilogue with bias/silu
        __syncthreads();
        #pragma unroll
        for (int i=0;i<2;i++)
            #pragma unroll
            for (int j=0;j<2;j++)
                wmma::store_matrix_sync(&Cs[(wr*32+i*16)*68 + wc*32 + j*16],
                                        c[i][j], 68, wmma::mem_row_major);
        __syncthreads();
        #pragma unroll
        for (int t=0;t<32;t++) {
            int idx = tid + (t<<8);              // 0..8191
            int r = idx >> 6, cc = idx & 63;
            float v = Cs[r*68 + cc] + bias[n0 + cc];
            if (EPI == 2) v = v / (1.f + __expf(-v));
            size_t gpos = (size_t)(m0+r)*N + n0 + cc;
            if (OUTH) scratch_h(cid)[gpos] = __float2half_rn(v);
            else      scratch_f(cid)[gpos] = v;
        }
    }
}

// =====================================================================
// Flash attention fp16 v2 (unchanged from R13, measured fast):
// Q tile 128, KV tiles 64, double-buffered cp.async, warp tile 32x32.
// QK fp16 mma -> fp32 S frags; exp on regs -> half accum frag -> sP;
// PV fp16 mma. Two barriers per KV tile. fp16 in/out. smem 74.2 KB.
// =====================================================================
#define PLDH 72
__global__ __launch_bounds__(256)
void attn_kernel()
{
    extern __shared__ __half smh[];
    __half* sQ = smh;                                   // 128x72
    __half* sK[2] = { smh + 9216,  smh + 13824 };       // 64x72 each
    __half* sV[2] = { smh + 18432, smh + 23040 };       // 64x72 each
    __half* sP = smh + 27648;                           // 128x72
    float*  sL = (float*)(smh + 36864);                 // 128 floats
    float*  sO = (float*)(smh + 9216);                  // 128x68 fp32, reuse sK/sV at end

    const int bh = blockIdx.y;
    const int b  = bh >> 4, h = bh & 15;
    const int q0 = blockIdx.x << 7;
    const __half* Qh = g_Qh2 + (size_t)b*SEQ*CH + h*HDIM;
    const __half* Kh = g_Kh2 + (size_t)b*SEQ*CH + h*HDIM;
    const __half* Vh = g_Vh2 + (size_t)b*SEQ*CH + h*HDIM;

    const int tid  = threadIdx.x;
    const int warp = tid >> 5;
    const int wr   = warp >> 1;          // 0..3 (32-row strip)
    const int wc   = warp & 1;           // 0..1 (32-col strip)
    const int myrow = tid >> 1;          // 0..127
    const int cb    = (tid & 1) << 5;    // 32-col chunk

    // Q tile: 128 rows x 64 halfs = 1024 16B chunks, 4/thread
    #pragma unroll
    for (int i=0;i<4;i++) {
        int cch = tid + (i<<8);
        int r = cch >> 3, col = (cch & 7) << 3;
        *(uint4*)&sQ[r*PLDH + col] = *(const uint4*)&Qh[(size_t)(q0+r)*CH + col];
    }

    wmma::fragment<wmma::accumulator,16,16,16,float> o[2][2];
    #pragma unroll
    for (int i=0;i<2;i++)
        #pragma unroll
        for (int j=0;j<2;j++) wmma::fill_fragment(o[i][j], 0.f);
    float l = 0.f;

    // prologue: KV stage 0 (64x64 halfs = 512 chunks each, 2/thread)
    #pragma unroll
    for (int i=0;i<2;i++) {
        int cch = tid + (i<<8);
        int r = cch >> 3, col = (cch & 7) << 3;
        cp16(&sK[0][r*PLDH + col], &Kh[(size_t)r*CH + col]);
        cp16(&sV[0][r*PLDH + col], &Vh[(size_t)r*CH + col]);
    }
    cp_commit();

    const int NT = SEQ / 64;
    for (int it=0; it<NT; it++) {
        const int buf = it & 1;
        cp_wait<0>();
        __syncthreads();                 // KV(buf) ready; buf^1, sP free
        if (it+1 < NT) {
            const int kt = (it+1) << 6;
            #pragma unroll
            for (int i=0;i<2;i++) {
                int cch = tid + (i<<8);
                int r = cch >> 3, col = (cch & 7) << 3;
                cp16(&sK[buf^1][r*PLDH + col], &Kh[(size_t)(kt+r)*CH + col]);
                cp16(&sV[buf^1][r*PLDH + col], &Vh[(size_t)(kt+r)*CH + col]);
            }
            cp_commit();
        }

        // ---- S(128x64) = Q @ K^T : fp32 accum frags ----
        wmma::fragment<wmma::accumulator,16,16,16,float> s[2][2];
        #pragma unroll
        for (int i=0;i<2;i++)
            #pragma unroll
            for (int j=0;j<2;j++) wmma::fill_fragment(s[i][j], 0.f);
        #pragma unroll
        for (int kk=0; kk<64; kk+=16) {
            wmma::fragment<wmma::matrix_a,16,16,16,__half,wmma::row_major> a[2];
            wmma::fragment<wmma::matrix_b,16,16,16,__half,wmma::col_major> bf[2];
            #pragma unroll
            for (int i=0;i<2;i++)
                wmma::load_matrix_sync(a[i], &sQ[(wr*32+i*16)*PLDH + kk], PLDH);
            #pragma unroll
            for (int j=0;j<2;j++)
                wmma::load_matrix_sync(bf[j], &sK[buf][(wc*32+j*16)*PLDH + kk], PLDH);
            #pragma unroll
            for (int i=0;i<2;i++)
                #pragma unroll
                for (int j=0;j<2;j++)
                    wmma::mma_sync(s[i][j], a[i], bf[j], s[i][j]);
        }

        // ---- P = exp(S*scale) on regs -> half accum frag -> sP ----
        #pragma unroll
        for (int i=0;i<2;i++)
            #pragma unroll
            for (int j=0;j<2;j++) {
                wmma::fragment<wmma::accumulator,16,16,16,__half> hp;
                #pragma unroll
                for (int t=0;t<hp.num_elements;t++)
                    hp.x[t] = __float2half_rn(__expf(s[i][j].x[t] * 0.125f));
                wmma::store_matrix_sync(&sP[(wr*32+i*16)*PLDH + wc*32 + j*16], hp,
                                        PLDH, wmma::mem_row_major);
            }
        __syncthreads();                 // P visible

        // ---- per-thread partial row sum from sP ----
        {
            const __half* bp = &sP[myrow*PLDH + cb];
            #pragma unroll
            for (int t=0;t<16;t++) {
                float2 p2 = __half22float2(*(const __half2*)&bp[t*2]);
                l += p2.x + p2.y;
            }
        }

        // ---- O(128x64) += P(128x64) @ V(64x64) ----
        #pragma unroll
        for (int kk=0; kk<64; kk+=16) {
            wmma::fragment<wmma::matrix_a,16,16,16,__half,wmma::row_major> pa[2];
            wmma::fragment<wmma::matrix_b,16,16,16,__half,wmma::row_major> vb[2];
            #pragma unroll
            for (int i=0;i<2;i++)
                wmma::load_matrix_sync(pa[i], &sP[(wr*32+i*16)*PLDH + kk], PLDH);
            #pragma unroll
            for (int j=0;j<2;j++)
                wmma::load_matrix_sync(vb[j], &sV[buf][kk*PLDH + wc*32 + j*16], PLDH);
            #pragma unroll
            for (int i=0;i<2;i++)
                #pragma unroll
                for (int j=0;j<2;j++)
                    wmma::mma_sync(o[i][j], pa[i], vb[j], o[i][j]);
        }
    }

    l += __shfl_xor_sync(0xffffffffu, l, 1);
    if ((tid & 1) == 0) sL[myrow] = 1.f / l;
    __syncthreads();                     // all PV done; sK/sV region free

    #pragma unroll
    for (int i=0;i<2;i++)
        #pragma unroll
        for (int j=0;j<2;j++)
            wmma::store_matrix_sync(&sO[(wr*32+i*16)*68 + wc*32 + j*16], o[i][j],
                                    68, wmma::mem_row_major);
    __syncthreads();

    #pragma unroll
    for (int t=0;t<32;t++) {
        int idx = tid + (t<<8);
        int r = idx >> 6, cc = idx & 63;
        g_attnh[(size_t)(b*SEQ + q0 + r)*CH + h*HDIM + cc] =
            __float2half_rn(sO[r*68+cc] * sL[r]);
    }
}

// =====================================================================
// Fused residual + LayerNorm (fp32), float4-vectorized.
// Optional extra fp16 output copy.
// =====================================================================
__global__ __launch_bounds__(256)
void ln_kernel(int aidf, const float* __restrict__ Rext, int ridf,
               const float* __restrict__ g, const float* __restrict__ bb,
               float* __restrict__ Oext, int oidf, int oidh)
{
    const float* A = scratch_f(aidf);
    const float* R = Rext ? Rext : scratch_f(ridf);
    float* out = Oext ? Oext : scratch_f(oidf);
    __half* outh = (oidh > 0) ? scratch_h(oidh) : nullptr;

    __shared__ float s1[8], s2[8];
    const int row = blockIdx.x;
    const size_t base = (size_t)row * CH;
    const int tid = threadIdx.x;

    float4 a4 = ((const float4*)(A + base))[tid];
    float4 r4 = ((const float4*)(R + base))[tid];
    float v0 = a4.x + r4.x, v1 = a4.y + r4.y, v2 = a4.z + r4.z, v3 = a4.w + r4.w;
    float sum = v0 + v1 + v2 + v3;
    float sq  = v0*v0 + v1*v1 + v2*v2 + v3*v3;

    #pragma unroll
    for (int o=16;o;o>>=1) {
        sum += __shfl_xor_sync(0xffffffffu, sum, o);
        sq  += __shfl_xor_sync(0xffffffffu, sq,  o);
    }
    if ((tid & 31) == 0) { s1[tid>>5] = sum; s2[tid>>5] = sq; }
    __syncthreads();
    if (tid < 32) {
        float a = (tid < 8) ? s1[tid] : 0.f;
        float b2 = (tid < 8) ? s2[tid] : 0.f;
        #pragma unroll
        for (int o=4;o;o>>=1) {
            a  += __shfl_xor_sync(0xffffffffu, a,  o);
            b2 += __shfl_xor_sync(0xffffffffu, b2, o);
        }
        if (tid == 0) { s1[0] = a; s2[0] = b2; }
    }
    __syncthreads();
    float mean = s1[0] * (1.f/CH);
    float var  = s2[0] * (1.f/CH) - mean*mean;
    float rstd = rsqrtf(var + 1e-5f);

    float4 g4 = ((const float4*)g)[tid];
    float4 b4 = ((const float4*)bb)[tid];
    float4 o4;
    o4.x = (v0 - mean) * rstd * g4.x + b4.x;
    o4.y = (v1 - mean) * rstd * g4.y + b4.y;
    o4.z = (v2 - mean) * rstd * g4.z + b4.z;
    o4.w = (v3 - mean) * rstd * g4.w + b4.w;
    ((float4*)(out + base))[tid] = o4;
    if (outh) {
        __half2* oh2 = (__half2*)(outh + base);
        oh2[tid*2]   = __floats2half2_rn(o4.x, o4.y);
        oh2[tid*2+1] = __floats2half2_rn(o4.z, o4.w);
    }
}

// =====================================================================
extern "C" void kernel_launch(void* const* d_in, const int* in_sizes, int n_in,
                              void* d_out, int out_size)
{
    const float *x, *keys, *Wq, *Wk, *Wv, *Wo, *ln1_g, *ln1_b;
    const float *fc1_w, *fc1_b, *fc2_w, *fc2_b, *ln2_g, *ln2_b;

    if (in_sizes[0] == MROWS*CH) {
        x     = (const float*)d_in[0];
        keys  = (const float*)d_in[1];
        Wq    = (const float*)d_in[2];
        Wk    = (const float*)d_in[3];
        Wv    = (const float*)d_in[4];
        Wo    = (const float*)d_in[5];
        ln1_g = (const float*)d_in[6];
        ln1_b = (const float*)d_in[7];
        fc1_w = (const float*)d_in[8];
        fc1_b = (const float*)d_in[9];
        fc2_w = (const float*)d_in[10];
        fc2_b = (const float*)d_in[11];
        ln2_g = (const float*)d_in[12];
        ln2_b = (const float*)d_in[13];
    } else {
        Wk    = (const float*)d_in[0];
        Wo    = (const float*)d_in[1];
        Wq    = (const float*)d_in[2];
        Wv    = (const float*)d_in[3];
        fc1_b = (const float*)d_in[4];
        fc1_w = (const float*)d_in[5];
        fc2_b = (const float*)d_in[6];
        fc2_w = (const float*)d_in[7];
        keys  = (const float*)d_in[8];
        ln1_b = (const float*)d_in[9];
        ln1_g = (const float*)d_in[10];
        ln2_b = (const float*)d_in[11];
        ln2_g = (const float*)d_in[12];
        x     = (const float*)d_in[13];
    }
    float* out = (float*)d_out;

    const int GEMM_SMEM = 27648 * (int)sizeof(__half);           // 55296 B
    const int ATTN_SMEM = 36864 * (int)sizeof(__half) + 512;     // 74240 B
    cudaFuncSetAttribute(gemm_h<0,1>, cudaFuncAttributeMaxDynamicSharedMemorySize, GEMM_SMEM);
    cudaFuncSetAttribute(gemm_h<0,0>, cudaFuncAttributeMaxDynamicSharedMemorySize, GEMM_SMEM);
    cudaFuncSetAttribute(gemm_h<2,1>, cudaFuncAttributeMaxDynamicSharedMemorySize, GEMM_SMEM);
    cudaFuncSetAttribute(gemm_h<1,0>, cudaFuncAttributeMaxDynamicSharedMemorySize, GEMM_SMEM);
    cudaFuncSetAttribute(attn_kernel, cudaFuncAttributeMaxDynamicSharedMemorySize, ATTN_SMEM);

    dim3 blk(256);
    dim3 g1024(CH/64, MROWS/128);     // (16, 64)
    dim3 g2048(FF/64, MROWS/128);     // (32, 64)

    // 0) fp32 -> fp16 conversion of inputs + weights
    conv8<<<2048, blk>>>(x, keys, Wq, Wk, Wv, Wo, fc1_w, fc2_w);

    // 1) QKV projections (fp16 in, fp16 out, direct-store epilogue)
    gemm_h<0,1><<<g1024, blk, GEMM_SMEM>>>(1, 3, nullptr, 9,  MROWS, CH, CH);  // Qh2
    gemm_h<0,1><<<g1024, blk, GEMM_SMEM>>>(2, 4, nullptr, 10, MROWS, CH, CH);  // Kh2
    gemm_h<0,1><<<g1024, blk, GEMM_SMEM>>>(2, 5, nullptr, 11, MROWS, CH, CH);  // Vh2

    // 2) attention: fp16 Q/K/V -> fp16 attnh
    dim3 ga(SEQ/128, BATCH*NHEAD);
    attn_kernel<<<ga, blk, ATTN_SMEM>>>();

    // 3) output projection (direct fp32 store) + residual LN
    gemm_h<0,0><<<g1024, blk, GEMM_SMEM>>>(12, 6, nullptr, 1, MROWS, CH, CH);  // g_O
    ln_kernel<<<MROWS, blk>>>(1, x, 0, ln1_g, ln1_b, nullptr, 2, 13);          // g_int + g_inth

    // 4) MLP
    gemm_h<2,1><<<g2048, blk, GEMM_SMEM>>>(13, 7, fc1_b, 14, MROWS, FF, CH);   // H1h
    gemm_h<1,0><<<g1024, blk, GEMM_SMEM>>>(14, 8, fc2_b, 3,  MROWS, CH, FF);   // g_F
    ln_kernel<<<MROWS, blk>>>(3, nullptr, 2, ln2_g, ln2_b, out, 0, 0);
}

// round 16
// speedup vs baseline: 1.0196x; 1.0051x over previous
#include <cuda_runtime.h>
#include <cuda_fp16.h>
#include <cstdint>
#include <mma.h>

using namespace nvcuda;

// ---------------- problem constants ----------------
#define BATCH 4
#define SEQ   2048
#define CH    1024
#define FF    2048
#define NHEAD 16
#define HDIM  64
#define MROWS (BATCH*SEQ)            // 8192
#define NELEM ((size_t)MROWS*CH)     // 8388608

// ---------------- scratch (no cudaMalloc allowed) ----------------
__device__ __half g_xh   [NELEM];
__device__ __half g_keysh[NELEM];
__device__ __half g_Wqh  [CH*CH];
__device__ __half g_Wkh  [CH*CH];
__device__ __half g_Wvh  [CH*CH];
__device__ __half g_Woh  [CH*CH];
__device__ __half g_fc1h [FF*CH];
__device__ __half g_fc2h [CH*FF];
__device__ __half g_Qh2  [NELEM];
__device__ __half g_Kh2  [NELEM];
__device__ __half g_Vh2  [NELEM];
__device__ __half g_attnh[NELEM];
__device__ __half g_inth [NELEM];
__device__ __half g_H1h  [(size_t)MROWS*FF];
__device__ float  g_O  [NELEM];
__device__ float  g_int[NELEM];
__device__ float  g_F  [NELEM];

__device__ __forceinline__ __half* scratch_h(int id) {
    switch (id) {
        case 1:  return g_xh;    case 2:  return g_keysh;
        case 3:  return g_Wqh;   case 4:  return g_Wkh;
        case 5:  return g_Wvh;   case 6:  return g_Woh;
        case 7:  return g_fc1h;  case 8:  return g_fc2h;
        case 9:  return g_Qh2;   case 10: return g_Kh2;
        case 11: return g_Vh2;   case 12: return g_attnh;
        case 13: return g_inth;  case 14: return g_H1h;
    }
    return nullptr;
}
__device__ __forceinline__ float* scratch_f(int id) {
    switch (id) {
        case 1: return g_O;  case 2: return g_int; case 3: return g_F;
    }
    return nullptr;
}

// ---------------- cp.async helpers ----------------
__device__ __forceinline__ void cp16(void* smem_dst, const void* gsrc) {
    unsigned int s = (unsigned int)__cvta_generic_to_shared(smem_dst);
    asm volatile("cp.async.cg.shared.global [%0], [%1], 16;" :: "r"(s), "l"(gsrc));
}
__device__ __forceinline__ void cp_commit() {
    asm volatile("cp.async.commit_group;");
}
template<int N>
__device__ __forceinline__ void cp_wait() {
    asm volatile("cp.async.wait_group %0;" :: "n"(N));
}

// =====================================================================
// conv8: fp32 -> fp16 for x, keys and the six weight matrices.
// =====================================================================
__global__ __launch_bounds__(256)
void conv8(const float* __restrict__ x, const float* __restrict__ keys,
           const float* __restrict__ wq, const float* __restrict__ wk,
           const float* __restrict__ wv, const float* __restrict__ wo,
           const float* __restrict__ f1, const float* __restrict__ f2)
{
    const size_t T = 6291456;   // total float4 chunks
    for (size_t i = (size_t)blockIdx.x*blockDim.x + threadIdx.x; i < T;
         i += (size_t)gridDim.x*blockDim.x) {
        const float* src; __half* dst; size_t off;
        if      (i < 2097152) { src=x;    dst=g_xh;    off=i; }
        else if (i < 4194304) { src=keys; dst=g_keysh; off=i-2097152; }
        else if (i < 4456448) { src=wq;   dst=g_Wqh;   off=i-4194304; }
        else if (i < 4718592) { src=wk;   dst=g_Wkh;   off=i-4456448; }
        else if (i < 4980736) { src=wv;   dst=g_Wvh;   off=i-4718592; }
        else if (i < 5242880) { src=wo;   dst=g_Woh;   off=i-4980736; }
        else if (i < 5767168) { src=f1;   dst=g_fc1h;  off=i-5242880; }
        else                  { src=f2;   dst=g_fc2h;  off=i-5767168; }
        float4 v = ((const float4*)src)[off];
        __half2* d2 = (__half2*)dst;
        d2[off*2]   = __floats2half2_rn(v.x, v.y);
        d2[off*2+1] = __floats2half2_rn(v.z, v.w);
    }
}

// =====================================================================
// Shared GEMM mainloop body (128x64 tile, BK=64, 8 warps, warp 32x32).
// Returns with accumulators filled; caller does the epilogue.
// =====================================================================
#define GLDH 72
struct GemmAcc { wmma::fragment<wmma::accumulator,16,16,16,float> c[2][2]; };

__device__ __forceinline__ void gemm_mainloop(
    const __half* __restrict__ A, const __half* __restrict__ B,
    __half* smh, int m0, int n0, int K, int tid, int wr, int wc, GemmAcc& acc)
{
    __half* As[2] = { smh,         smh + 9216  };   // 128 x 72 each
    __half* Bs[2] = { smh + 18432, smh + 23040 };   // 64 x 72 each

    #pragma unroll
    for (int i=0;i<2;i++)
        #pragma unroll
        for (int j=0;j<2;j++) wmma::fill_fragment(acc.c[i][j], 0.f);

    const int NS = K >> 6;

    #pragma unroll
    for (int i=0;i<4;i++) {
        int cch = tid + (i<<8);
        int r = cch >> 3, col = (cch & 7) << 3;
        cp16(&As[0][r*GLDH + col], &A[(size_t)(m0+r)*K + col]);
    }
    #pragma unroll
    for (int i=0;i<2;i++) {
        int cch = tid + (i<<8);
        int r = cch >> 3, col = (cch & 7) << 3;
        cp16(&Bs[0][r*GLDH + col], &B[(size_t)(n0+r)*K + col]);
    }
    cp_commit();

    for (int s=0; s<NS; s++) {
        const int buf = s & 1;
        cp_wait<0>();
        __syncthreads();
        if (s+1 < NS) {
            const int k0 = (s+1) << 6;
            #pragma unroll
            for (int i=0;i<4;i++) {
                int cch = tid + (i<<8);
                int r = cch >> 3, col = (cch & 7) << 3;
                cp16(&As[buf^1][r*GLDH + col], &A[(size_t)(m0+r)*K + k0 + col]);
            }
            #pragma unroll
            for (int i=0;i<2;i++) {
                int cch = tid + (i<<8);
                int r = cch >> 3, col = (cch & 7) << 3;
                cp16(&Bs[buf^1][r*GLDH + col], &B[(size_t)(n0+r)*K + k0 + col]);
            }
            cp_commit();
        }

        #pragma unroll
        for (int kk=0; kk<64; kk+=16) {
            wmma::fragment<wmma::matrix_a,16,16,16,__half,wmma::row_major> a[2];
            wmma::fragment<wmma::matrix_b,16,16,16,__half,wmma::col_major> bf[2];
            #pragma unroll
            for (int i=0;i<2;i++)
                wmma::load_matrix_sync(a[i], &As[buf][(wr*32+i*16)*GLDH + kk], GLDH);
            #pragma unroll
            for (int j=0;j<2;j++)
                wmma::load_matrix_sync(bf[j], &Bs[buf][(wc*32+j*16)*GLDH + kk], GLDH);
            #pragma unroll
            for (int i=0;i<2;i++)
                #pragma unroll
                for (int j=0;j<2;j++)
                    wmma::mma_sync(acc.c[i][j], a[i], bf[j], acc.c[i][j]);
        }
    }
}

// direct half store of accumulators (no smem, no barriers)
__device__ __forceinline__ void store_acc_half(
    GemmAcc& acc, __half* C, int m0, int n0, int N, int wr, int wc)
{
    #pragma unroll
    for (int i=0;i<2;i++)
        #pragma unroll
        for (int j=0;j<2;j++) {
            wmma::fragment<wmma::accumulator,16,16,16,__half> hc;
            #pragma unroll
            for (int t=0;t<hc.num_elements;t++)
                hc.x[t] = __float2half_rn(acc.c[i][j].x[t]);
            wmma::store_matrix_sync(
                &C[(size_t)(m0+wr*32+i*16)*N + n0 + wc*32 + j*16],
                hc, N, wmma::mem_row_major);
        }
}

// =====================================================================
// Merged QKV GEMM: blockIdx.z selects (A, B, C) among the three
// independent projections. 3072 CTAs in one launch -> ~6.9 full waves.
// =====================================================================
__global__ __launch_bounds__(256, 3)
void gemm_qkv()
{
    extern __shared__ __half smh[];
    const int z = blockIdx.z;
    const __half* A = (z == 0) ? g_xh : g_keysh;
    const __half* B = (z == 0) ? g_Wqh : (z == 1) ? g_Wkh : g_Wvh;
    __half*       C = (z == 0) ? g_Qh2 : (z == 1) ? g_Kh2 : g_Vh2;

    const int m0 = blockIdx.y << 7;
    const int n0 = blockIdx.x << 6;
    const int tid  = threadIdx.x;
    const int warp = tid >> 5;
    const int wr = warp >> 1, wc = warp & 1;

    GemmAcc acc;
    gemm_mainloop(A, B, smh, m0, n0, CH, tid, wr, wc, acc);
    store_acc_half(acc, C, m0, n0, CH, wr, wc);
}

// =====================================================================
// Generic GEMM (Wo / fc1 / fc2): EPI 0:none 1:+bias 2:+bias+silu
// OUTH=1: fp16 out; OUTH=0: fp32 out.
// =====================================================================
template<int EPI, int OUTH>
__global__ __launch_bounds__(256, 3)
void gemm_h(int aid, int bid, const float* __restrict__ bias,
            int cid, int M, int N, int K)
{
    extern __shared__ __half smh[];
    const __half* A = scratch_h(aid);
    const __half* B = scratch_h(bid);
    float* Cs = (float*)smh;

    const int m0 = blockIdx.y << 7;
    const int n0 = blockIdx.x << 6;
    const int tid  = threadIdx.x;
    const int warp = tid >> 5;
    const int wr = warp >> 1, wc = warp & 1;

    GemmAcc acc;
    gemm_mainloop(A, B, smh, m0, n0, K, tid, wr, wc, acc);

    if (EPI == 0) {
        if (OUTH) {
            store_acc_half(acc, scratch_h(cid), m0, n0, N, wr, wc);
        } else {
            float* C = scratch_f(cid);
            #pragma unroll
            for (int i=0;i<2;i++)
                #pragma unroll
                for (int j=0;j<2;j++)
                    wmma::store_matrix_sync(
                        &C[(size_t)(m0+wr*32+i*16)*N + n0 + wc*32 + j*16],
                        acc.c[i][j], N, wmma::mem_row_major);
        }
    } else {
        __syncthreads();
        #pragma unroll
        for (int i=0;i<2;i++)
            #pragma unroll
            for (int j=0;j<2;j++)
                wmma::store_matrix_sync(&Cs[(wr*32+i*16)*68 + wc*32 + j*16],
                                        acc.c[i][j], 68, wmma::mem_row_major);
        __syncthreads();
        #pragma unroll
        for (int t=0;t<32;t++) {
            int idx = tid + (t<<8);
            int r = idx >> 6, cc = idx & 63;
            float v = Cs[r*68 + cc] + bias[n0 + cc];
            if (EPI == 2) v = v / (1.f + __expf(-v));
            size_t gpos = (size_t)(m0+r)*N + n0 + cc;
            if (OUTH) scratch_h(cid)[gpos] = __float2half_rn(v);
            else      scratch_f(cid)[gpos] = v;
        }
    }
}

// =====================================================================
// Flash attention fp16 (unchanged from R13/R15, measured fast).
// =====================================================================
#define PLDH 72
__global__ __launch_bounds__(256)
void attn_kernel()
{
    extern __shared__ __half smh[];
    __half* sQ = smh;                                   // 128x72
    __half* sK[2] = { smh + 9216,  smh + 13824 };       // 64x72 each
    __half* sV[2] = { smh + 18432, smh + 23040 };       // 64x72 each
    __half* sP = smh + 27648;                           // 128x72
    float*  sL = (float*)(smh + 36864);                 // 128 floats
    float*  sO = (float*)(smh + 9216);                  // 128x68 fp32, reuse

    const int bh = blockIdx.y;
    const int b  = bh >> 4, h = bh & 15;
    const int q0 = blockIdx.x << 7;
    const __half* Qh = g_Qh2 + (size_t)b*SEQ*CH + h*HDIM;
    const __half* Kh = g_Kh2 + (size_t)b*SEQ*CH + h*HDIM;
    const __half* Vh = g_Vh2 + (size_t)b*SEQ*CH + h*HDIM;

    const int tid  = threadIdx.x;
    const int warp = tid >> 5;
    const int wr   = warp >> 1;
    const int wc   = warp & 1;
    const int myrow = tid >> 1;
    const int cb    = (tid & 1) << 5;

    #pragma unroll
    for (int i=0;i<4;i++) {
        int cch = tid + (i<<8);
        int r = cch >> 3, col = (cch & 7) << 3;
        *(uint4*)&sQ[r*PLDH + col] = *(const uint4*)&Qh[(size_t)(q0+r)*CH + col];
    }

    wmma::fragment<wmma::accumulator,16,16,16,float> o[2][2];
    #pragma unroll
    for (int i=0;i<2;i++)
        #pragma unroll
        for (int j=0;j<2;j++) wmma::fill_fragment(o[i][j], 0.f);
    float l = 0.f;

    #pragma unroll
    for (int i=0;i<2;i++) {
        int cch = tid + (i<<8);
        int r = cch >> 3, col = (cch & 7) << 3;
        cp16(&sK[0][r*PLDH + col], &Kh[(size_t)r*CH + col]);
        cp16(&sV[0][r*PLDH + col], &Vh[(size_t)r*CH + col]);
    }
    cp_commit();

    const int NT = SEQ / 64;
    for (int it=0; it<NT; it++) {
        const int buf = it & 1;
        cp_wait<0>();
        __syncthreads();
        if (it+1 < NT) {
            const int kt = (it+1) << 6;
            #pragma unroll
            for (int i=0;i<2;i++) {
                int cch = tid + (i<<8);
                int r = cch >> 3, col = (cch & 7) << 3;
                cp16(&sK[buf^1][r*PLDH + col], &Kh[(size_t)(kt+r)*CH + col]);
                cp16(&sV[buf^1][r*PLDH + col], &Vh[(size_t)(kt+r)*CH + col]);
            }
            cp_commit();
        }

        wmma::fragment<wmma::accumulator,16,16,16,float> s[2][2];
        #pragma unroll
        for (int i=0;i<2;i++)
            #pragma unroll
            for (int j=0;j<2;j++) wmma::fill_fragment(s[i][j], 0.f);
        #pragma unroll
        for (int kk=0; kk<64; kk+=16) {
            wmma::fragment<wmma::matrix_a,16,16,16,__half,wmma::row_major> a[2];
            wmma::fragment<wmma::matrix_b,16,16,16,__half,wmma::col_major> bf[2];
            #pragma unroll
            for (int i=0;i<2;i++)
                wmma::load_matrix_sync(a[i], &sQ[(wr*32+i*16)*PLDH + kk], PLDH);
            #pragma unroll
            for (int j=0;j<2;j++)
                wmma::load_matrix_sync(bf[j], &sK[buf][(wc*32+j*16)*PLDH + kk], PLDH);
            #pragma unroll
            for (int i=0;i<2;i++)
                #pragma unroll
                for (int j=0;j<2;j++)
                    wmma::mma_sync(s[i][j], a[i], bf[j], s[i][j]);
        }

        #pragma unroll
        for (int i=0;i<2;i++)
            #pragma unroll
            for (int j=0;j<2;j++) {
                wmma::fragment<wmma::accumulator,16,16,16,__half> hp;
                #pragma unroll
                for (int t=0;t<hp.num_elements;t++)
                    hp.x[t] = __float2half_rn(__expf(s[i][j].x[t] * 0.125f));
                wmma::store_matrix_sync(&sP[(wr*32+i*16)*PLDH + wc*32 + j*16], hp,
                                        PLDH, wmma::mem_row_major);
            }
        __syncthreads();

        {
            const __half* bp = &sP[myrow*PLDH + cb];
            #pragma unroll
            for (int t=0;t<16;t++) {
                float2 p2 = __half22float2(*(const __half2*)&bp[t*2]);
                l += p2.x + p2.y;
            }
        }

        #pragma unroll
        for (int kk=0; kk<64; kk+=16) {
            wmma::fragment<wmma::matrix_a,16,16,16,__half,wmma::row_major> pa[2];
            wmma::fragment<wmma::matrix_b,16,16,16,__half,wmma::row_major> vb[2];
            #pragma unroll
            for (int i=0;i<2;i++)
                wmma::load_matrix_sync(pa[i], &sP[(wr*32+i*16)*PLDH + kk], PLDH);
            #pragma unroll
            for (int j=0;j<2;j++)
                wmma::load_matrix_sync(vb[j], &sV[buf][kk*PLDH + wc*32 + j*16], PLDH);
            #pragma unroll
            for (int i=0;i<2;i++)
                #pragma unroll
                for (int j=0;j<2;j++)
                    wmma::mma_sync(o[i][j], pa[i], vb[j], o[i][j]);
        }
    }

    l += __shfl_xor_sync(0xffffffffu, l, 1);
    if ((tid & 1) == 0) sL[myrow] = 1.f / l;
    __syncthreads();

    #pragma unroll
    for (int i=0;i<2;i++)
        #pragma unroll
        for (int j=0;j<2;j++)
            wmma::store_matrix_sync(&sO[(wr*32+i*16)*68 + wc*32 + j*16], o[i][j],
                                    68, wmma::mem_row_major);
    __syncthreads();

    #pragma unroll
    for (int t=0;t<32;t++) {
        int idx = tid + (t<<8);
        int r = idx >> 6, cc = idx & 63;
        g_attnh[(size_t)(b*SEQ + q0 + r)*CH + h*HDIM + cc] =
            __float2half_rn(sO[r*68+cc] * sL[r]);
    }
}

// =====================================================================
// Fused residual + LayerNorm (fp32), float4-vectorized.
// =====================================================================
__global__ __launch_bounds__(256)
void ln_kernel(int aidf, const float* __restrict__ Rext, int ridf,
               const float* __restrict__ g, const float* __restrict__ bb,
               float* __restrict__ Oext, int oidf, int oidh)
{
    const float* A = scratch_f(aidf);
    const float* R = Rext ? Rext : scratch_f(ridf);
    float* out = Oext ? Oext : scratch_f(oidf);
    __half* outh = (oidh > 0) ? scratch_h(oidh) : nullptr;

    __shared__ float s1[8], s2[8];
    const int row = blockIdx.x;
    const size_t base = (size_t)row * CH;
    const int tid = threadIdx.x;

    float4 a4 = ((const float4*)(A + base))[tid];
    float4 r4 = ((const float4*)(R + base))[tid];
    float v0 = a4.x + r4.x, v1 = a4.y + r4.y, v2 = a4.z + r4.z, v3 = a4.w + r4.w;
    float sum = v0 + v1 + v2 + v3;
    float sq  = v0*v0 + v1*v1 + v2*v2 + v3*v3;

    #pragma unroll
    for (int o=16;o;o>>=1) {
        sum += __shfl_xor_sync(0xffffffffu, sum, o);
        sq  += __shfl_xor_sync(0xffffffffu, sq,  o);
    }
    if ((tid & 31) == 0) { s1[tid>>5] = sum; s2[tid>>5] = sq; }
    __syncthreads();
    if (tid < 32) {
        float a = (tid < 8) ? s1[tid] : 0.f;
        float b2 = (tid < 8) ? s2[tid] : 0.f;
        #pragma unroll
        for (int o=4;o;o>>=1) {
            a  += __shfl_xor_sync(0xffffffffu, a,  o);
            b2 += __shfl_xor_sync(0xffffffffu, b2, o);
        }
        if (tid == 0) { s1[0] = a; s2[0] = b2; }
    }
    __syncthreads();
    float mean = s1[0] * (1.f/CH);
    float var  = s2[0] * (1.f/CH) - mean*mean;
    float rstd = rsqrtf(var + 1e-5f);

    float4 g4 = ((const float4*)g)[tid];
    float4 b4 = ((const float4*)bb)[tid];
    float4 o4;
    o4.x = (v0 - mean) * rstd * g4.x + b4.x;
    o4.y = (v1 - mean) * rstd * g4.y + b4.y;
    o4.z = (v2 - mean) * rstd * g4.z + b4.z;
    o4.w = (v3 - mean) * rstd * g4.w + b4.w;
    ((float4*)(out + base))[tid] = o4;
    if (outh) {
        __half2* oh2 = (__half2*)(outh + base);
        oh2[tid*2]   = __floats2half2_rn(o4.x, o4.y);
        oh2[tid*2+1] = __floats2half2_rn(o4.z, o4.w);
    }
}

// =====================================================================
extern "C" void kernel_launch(void* const* d_in, const int* in_sizes, int n_in,
                              void* d_out, int out_size)
{
    const float *x, *keys, *Wq, *Wk, *Wv, *Wo, *ln1_g, *ln1_b;
    const float *fc1_w, *fc1_b, *fc2_w, *fc2_b, *ln2_g, *ln2_b;

    if (in_sizes[0] == MROWS*CH) {
        x     = (const float*)d_in[0];
        keys  = (const float*)d_in[1];
        Wq    = (const float*)d_in[2];
        Wk    = (const float*)d_in[3];
        Wv    = (const float*)d_in[4];
        Wo    = (const float*)d_in[5];
        ln1_g = (const float*)d_in[6];
        ln1_b = (const float*)d_in[7];
        fc1_w = (const float*)d_in[8];
        fc1_b = (const float*)d_in[9];
        fc2_w = (const float*)d_in[10];
        fc2_b = (const float*)d_in[11];
        ln2_g = (const float*)d_in[12];
        ln2_b = (const float*)d_in[13];
    } else {
        Wk    = (const float*)d_in[0];
        Wo    = (const float*)d_in[1];
        Wq    = (const float*)d_in[2];
        Wv    = (const float*)d_in[3];
        fc1_b = (const float*)d_in[4];
        fc1_w = (const float*)d_in[5];
        fc2_b = (const float*)d_in[6];
        fc2_w = (const float*)d_in[7];
        keys  = (const float*)d_in[8];
        ln1_b = (const float*)d_in[9];
        ln1_g = (const float*)d_in[10];
        ln2_b = (const float*)d_in[11];
        ln2_g = (const float*)d_in[12];
        x     = (const float*)d_in[13];
    }
    float* out = (float*)d_out;

    const int GEMM_SMEM = 27648 * (int)sizeof(__half);           // 55296 B
    const int ATTN_SMEM = 36864 * (int)sizeof(__half) + 512;     // 74240 B
    cudaFuncSetAttribute(gemm_qkv,    cudaFuncAttributeMaxDynamicSharedMemorySize, GEMM_SMEM);
    cudaFuncSetAttribute(gemm_h<0,0>, cudaFuncAttributeMaxDynamicSharedMemorySize, GEMM_SMEM);
    cudaFuncSetAttribute(gemm_h<2,1>, cudaFuncAttributeMaxDynamicSharedMemorySize, GEMM_SMEM);
    cudaFuncSetAttribute(gemm_h<1,0>, cudaFuncAttributeMaxDynamicSharedMemorySize, GEMM_SMEM);
    cudaFuncSetAttribute(attn_kernel, cudaFuncAttributeMaxDynamicSharedMemorySize, ATTN_SMEM);

    dim3 blk(256);
    dim3 gQKV(CH/64, MROWS/128, 3);   // (16, 64, 3) = 3072 CTAs, one launch
    dim3 g1024(CH/64, MROWS/128);     // (16, 64)
    dim3 g2048(FF/64, MROWS/128);     // (32, 64)

    // 0) fp32 -> fp16 conversion of inputs + weights
    conv8<<<2048, blk>>>(x, keys, Wq, Wk, Wv, Wo, fc1_w, fc2_w);

    // 1) QKV projections, merged into ONE launch (z selects Q/K/V)
    gemm_qkv<<<gQKV, blk, GEMM_SMEM>>>();

    // 2) attention: fp16 Q/K/V -> fp16 attnh
    dim3 ga(SEQ/128, BATCH*NHEAD);
    attn_kernel<<<ga, blk, ATTN_SMEM>>>();

    // 3) output projection (direct fp32 store) + residual LN
    gemm_h<0,0><<<g1024, blk, GEMM_SMEM>>>(12, 6, nullptr, 1, MROWS, CH, CH);  // g_O
    ln_kernel<<<MROWS, blk>>>(1, x, 0, ln1_g, ln1_b, nullptr, 2, 13);          // g_int + g_inth

    // 4) MLP
    gemm_h<2,1><<<g2048, blk, GEMM_SMEM>>>(13, 7, fc1_b, 14, MROWS, FF, CH);   // H1h
    gemm_h<1,0><<<g1024, blk, GEMM_SMEM>>>(14, 8, fc2_b, 3,  MROWS, CH, FF);   // g_F
    ln_kernel<<<MROWS, blk>>>(3, nullptr, 2, ln2_g, ln2_b, out, 0, 0);
}

// round 17
// speedup vs baseline: 1.0246x; 1.0048x over previous
#include <cuda_runtime.h>
#include <cuda_fp16.h>
#include <cstdint>
#include <mma.h>

using namespace nvcuda;

// ---------------- problem constants ----------------
#define BATCH 4
#define SEQ   2048
#define CH    1024
#define FF    2048
#define NHEAD 16
#define HDIM  64
#define MROWS (BATCH*SEQ)            // 8192
#define NELEM ((size_t)MROWS*CH)     // 8388608

// ---------------- scratch (no cudaMalloc allowed) ----------------
__device__ __half g_xh   [NELEM];
__device__ __half g_keysh[NELEM];
__device__ __half g_Wqh  [CH*CH];
__device__ __half g_Wkh  [CH*CH];
__device__ __half g_Wvh  [CH*CH];
__device__ __half g_Woh  [CH*CH];
__device__ __half g_fc1h [FF*CH];
__device__ __half g_fc2h [CH*FF];
__device__ __half g_Qh2  [NELEM];
__device__ __half g_Kh2  [NELEM];
__device__ __half g_Vh2  [NELEM];
__device__ __half g_attnh[NELEM];
__device__ __half g_inth [NELEM];
__device__ __half g_H1h  [(size_t)MROWS*FF];
__device__ float  g_O  [NELEM];
__device__ float  g_F  [NELEM];

__device__ __forceinline__ __half* scratch_h(int id) {
    switch (id) {
        case 1:  return g_xh;    case 2:  return g_keysh;
        case 3:  return g_Wqh;   case 4:  return g_Wkh;
        case 5:  return g_Wvh;   case 6:  return g_Woh;
        case 7:  return g_fc1h;  case 8:  return g_fc2h;
        case 9:  return g_Qh2;   case 10: return g_Kh2;
        case 11: return g_Vh2;   case 12: return g_attnh;
        case 13: return g_inth;  case 14: return g_H1h;
    }
    return nullptr;
}
__device__ __forceinline__ float* scratch_f(int id) {
    switch (id) {
        case 1: return g_O;  case 3: return g_F;
    }
    return nullptr;
}

// ---------------- cp.async helpers ----------------
__device__ __forceinline__ void cp16(void* smem_dst, const void* gsrc) {
    unsigned int s = (unsigned int)__cvta_generic_to_shared(smem_dst);
    asm volatile("cp.async.cg.shared.global [%0], [%1], 16;" :: "r"(s), "l"(gsrc));
}
__device__ __forceinline__ void cp_commit() {
    asm volatile("cp.async.commit_group;");
}
template<int N>
__device__ __forceinline__ void cp_wait() {
    asm volatile("cp.async.wait_group %0;" :: "n"(N));
}

// =====================================================================
// conv8: fp32 -> fp16 for x, keys and the six weight matrices.
// =====================================================================
__global__ __launch_bounds__(256)
void conv8(const float* __restrict__ x, const float* __restrict__ keys,
           const float* __restrict__ wq, const float* __restrict__ wk,
           const float* __restrict__ wv, const float* __restrict__ wo,
           const float* __restrict__ f1, const float* __restrict__ f2)
{
    const size_t T = 6291456;   // total float4 chunks
    for (size_t i = (size_t)blockIdx.x*blockDim.x + threadIdx.x; i < T;
         i += (size_t)gridDim.x*blockDim.x) {
        const float* src; __half* dst; size_t off;
        if      (i < 2097152) { src=x;    dst=g_xh;    off=i; }
        else if (i < 4194304) { src=keys; dst=g_keysh; off=i-2097152; }
        else if (i < 4456448) { src=wq;   dst=g_Wqh;   off=i-4194304; }
        else if (i < 4718592) { src=wk;   dst=g_Wkh;   off=i-4456448; }
        else if (i < 4980736) { src=wv;   dst=g_Wvh;   off=i-4718592; }
        else if (i < 5242880) { src=wo;   dst=g_Woh;   off=i-4980736; }
        else if (i < 5767168) { src=f1;   dst=g_fc1h;  off=i-5242880; }
        else                  { src=f2;   dst=g_fc2h;  off=i-5767168; }
        float4 v = ((const float4*)src)[off];
        __half2* d2 = (__half2*)dst;
        d2[off*2]   = __floats2half2_rn(v.x, v.y);
        d2[off*2+1] = __floats2half2_rn(v.z, v.w);
    }
}

// =====================================================================
// Shared GEMM mainloop (128x64 tile, BK=64, 8 warps, warp 32x32).
// =====================================================================
#define GLDH 72
struct GemmAcc { wmma::fragment<wmma::accumulator,16,16,16,float> c[2][2]; };

__device__ __forceinline__ void gemm_mainloop(
    const __half* __restrict__ A, const __half* __restrict__ B,
    __half* smh, int m0, int n0, int K, int tid, int wr, int wc, GemmAcc& acc)
{
    __half* As[2] = { smh,         smh + 9216  };   // 128 x 72 each
    __half* Bs[2] = { smh + 18432, smh + 23040 };   // 64 x 72 each

    #pragma unroll
    for (int i=0;i<2;i++)
        #pragma unroll
        for (int j=0;j<2;j++) wmma::fill_fragment(acc.c[i][j], 0.f);

    const int NS = K >> 6;

    #pragma unroll
    for (int i=0;i<4;i++) {
        int cch = tid + (i<<8);
        int r = cch >> 3, col = (cch & 7) << 3;
        cp16(&As[0][r*GLDH + col], &A[(size_t)(m0+r)*K + col]);
    }
    #pragma unroll
    for (int i=0;i<2;i++) {
        int cch = tid + (i<<8);
        int r = cch >> 3, col = (cch & 7) << 3;
        cp16(&Bs[0][r*GLDH + col], &B[(size_t)(n0+r)*K + col]);
    }
    cp_commit();

    for (int s=0; s<NS; s++) {
        const int buf = s & 1;
        cp_wait<0>();
        __syncthreads();
        if (s+1 < NS) {
            const int k0 = (s+1) << 6;
            #pragma unroll
            for (int i=0;i<4;i++) {
                int cch = tid + (i<<8);
                int r = cch >> 3, col = (cch & 7) << 3;
                cp16(&As[buf^1][r*GLDH + col], &A[(size_t)(m0+r)*K + k0 + col]);
            }
            #pragma unroll
            for (int i=0;i<2;i++) {
                int cch = tid + (i<<8);
                int r = cch >> 3, col = (cch & 7) << 3;
                cp16(&Bs[buf^1][r*GLDH + col], &B[(size_t)(n0+r)*K + k0 + col]);
            }
            cp_commit();
        }

        #pragma unroll
        for (int kk=0; kk<64; kk+=16) {
            wmma::fragment<wmma::matrix_a,16,16,16,__half,wmma::row_major> a[2];
            wmma::fragment<wmma::matrix_b,16,16,16,__half,wmma::col_major> bf[2];
            #pragma unroll
            for (int i=0;i<2;i++)
                wmma::load_matrix_sync(a[i], &As[buf][(wr*32+i*16)*GLDH + kk], GLDH);
            #pragma unroll
            for (int j=0;j<2;j++)
                wmma::load_matrix_sync(bf[j], &Bs[buf][(wc*32+j*16)*GLDH + kk], GLDH);
            #pragma unroll
            for (int i=0;i<2;i++)
                #pragma unroll
                for (int j=0;j<2;j++)
                    wmma::mma_sync(acc.c[i][j], a[i], bf[j], acc.c[i][j]);
        }
    }
}

// direct half store of accumulators (no smem, no barriers)
__device__ __forceinline__ void store_acc_half(
    GemmAcc& acc, __half* C, int m0, int n0, int N, int wr, int wc)
{
    #pragma unroll
    for (int i=0;i<2;i++)
        #pragma unroll
        for (int j=0;j<2;j++) {
            wmma::fragment<wmma::accumulator,16,16,16,__half> hc;
            #pragma unroll
            for (int t=0;t<hc.num_elements;t++)
                hc.x[t] = __float2half_rn(acc.c[i][j].x[t]);
            wmma::store_matrix_sync(
                &C[(size_t)(m0+wr*32+i*16)*N + n0 + wc*32 + j*16],
                hc, N, wmma::mem_row_major);
        }
}

// =====================================================================
// Merged QKV GEMM (one launch, blockIdx.z selects projection).
// =====================================================================
__global__ __launch_bounds__(256, 3)
void gemm_qkv()
{
    extern __shared__ __half smh[];
    const int z = blockIdx.z;
    const __half* A = (z == 0) ? g_xh : g_keysh;
    const __half* B = (z == 0) ? g_Wqh : (z == 1) ? g_Wkh : g_Wvh;
    __half*       C = (z == 0) ? g_Qh2 : (z == 1) ? g_Kh2 : g_Vh2;

    const int m0 = blockIdx.y << 7;
    const int n0 = blockIdx.x << 6;
    const int tid  = threadIdx.x;
    const int warp = tid >> 5;
    const int wr = warp >> 1, wc = warp & 1;

    GemmAcc acc;
    gemm_mainloop(A, B, smh, m0, n0, CH, tid, wr, wc, acc);
    store_acc_half(acc, C, m0, n0, CH, wr, wc);
}

// =====================================================================
// Generic GEMM (Wo / fc1 / fc2): EPI 0:none 1:+bias 2:+bias+silu
// OUTH=1: fp16 out; OUTH=0: fp32 out.
// EPI>0 uses a register epilogue: bias loaded as an accumulator frag
// from a 16-row-replicated smem tile (layout-agnostic), silu elementwise.
// =====================================================================
template<int EPI, int OUTH>
__global__ __launch_bounds__(256, 3)
void gemm_h(int aid, int bid, const float* __restrict__ bias,
            int cid, int M, int N, int K)
{
    extern __shared__ __half smh[];
    const __half* A = scratch_h(aid);
    const __half* B = scratch_h(bid);
    float* sbias = (float*)(smh + 27648);   // 16 x 68 fp32, after the K panels

    const int m0 = blockIdx.y << 7;
    const int n0 = blockIdx.x << 6;
    const int tid  = threadIdx.x;
    const int warp = tid >> 5;
    const int wr = warp >> 1, wc = warp & 1;

    if (EPI > 0) {
        // replicated bias tile: 16 identical rows of this CTA's 64-col slice
        for (int t = tid; t < 16*64; t += 256) {
            int r = t >> 6, cc = t & 63;
            sbias[r*68 + cc] = bias[n0 + cc];
        }
        // visibility guaranteed by the mainloop's first __syncthreads
    }

    GemmAcc acc;
    gemm_mainloop(A, B, smh, m0, n0, K, tid, wr, wc, acc);

    if (EPI > 0) {
        #pragma unroll
        for (int j=0;j<2;j++) {
            wmma::fragment<wmma::accumulator,16,16,16,float> bfr;
            wmma::load_matrix_sync(bfr, &sbias[wc*32 + j*16], 68, wmma::mem_row_major);
            #pragma unroll
            for (int i=0;i<2;i++) {
                #pragma unroll
                for (int t=0;t<bfr.num_elements;t++) {
                    float v = acc.c[i][j].x[t] + bfr.x[t];
                    if (EPI == 2) v = v / (1.f + __expf(-v));
                    acc.c[i][j].x[t] = v;
                }
            }
        }
    }

    if (OUTH) {
        store_acc_half(acc, scratch_h(cid), m0, n0, N, wr, wc);
    } else {
        float* C = scratch_f(cid);
        #pragma unroll
        for (int i=0;i<2;i++)
            #pragma unroll
            for (int j=0;j<2;j++)
                wmma::store_matrix_sync(
                    &C[(size_t)(m0+wr*32+i*16)*N + n0 + wc*32 + j*16],
                    acc.c[i][j], N, wmma::mem_row_major);
    }
}

// =====================================================================
// Flash attention fp16 (unchanged from R13/R16, passing).
// =====================================================================
#define PLDH 72
__global__ __launch_bounds__(256)
void attn_kernel()
{
    extern __shared__ __half smh[];
    __half* sQ = smh;                                   // 128x72
    __half* sK[2] = { smh + 9216,  smh + 13824 };       // 64x72 each
    __half* sV[2] = { smh + 18432, smh + 23040 };       // 64x72 each
    __half* sP = smh + 27648;                           // 128x72
    float*  sL = (float*)(smh + 36864);                 // 128 floats
    float*  sO = (float*)(smh + 9216);                  // 128x68 fp32, reuse

    const int bh = blockIdx.y;
    const int b  = bh >> 4, h = bh & 15;
    const int q0 = blockIdx.x << 7;
    const __half* Qh = g_Qh2 + (size_t)b*SEQ*CH + h*HDIM;
    const __half* Kh = g_Kh2 + (size_t)b*SEQ*CH + h*HDIM;
    const __half* Vh = g_Vh2 + (size_t)b*SEQ*CH + h*HDIM;

    const int tid  = threadIdx.x;
    const int warp = tid >> 5;
    const int wr   = warp >> 1;
    const int wc   = warp & 1;
    const int myrow = tid >> 1;
    const int cb    = (tid & 1) << 5;

    #pragma unroll
    for (int i=0;i<4;i++) {
        int cch = tid + (i<<8);
        int r = cch >> 3, col = (cch & 7) << 3;
        *(uint4*)&sQ[r*PLDH + col] = *(const uint4*)&Qh[(size_t)(q0+r)*CH + col];
    }

    wmma::fragment<wmma::accumulator,16,16,16,float> o[2][2];
    #pragma unroll
    for (int i=0;i<2;i++)
        #pragma unroll
        for (int j=0;j<2;j++) wmma::fill_fragment(o[i][j], 0.f);
    float l = 0.f;

    #pragma unroll
    for (int i=0;i<2;i++) {
        int cch = tid + (i<<8);
        int r = cch >> 3, col = (cch & 7) << 3;
        cp16(&sK[0][r*PLDH + col], &Kh[(size_t)r*CH + col]);
        cp16(&sV[0][r*PLDH + col], &Vh[(size_t)r*CH + col]);
    }
    cp_commit();

    const int NT = SEQ / 64;
    for (int it=0; it<NT; it++) {
        const int buf = it & 1;
        cp_wait<0>();
        __syncthreads();
        if (it+1 < NT) {
            const int kt = (it+1) << 6;
            #pragma unroll
            for (int i=0;i<2;i++) {
                int cch = tid + (i<<8);
                int r = cch >> 3, col = (cch & 7) << 3;
                cp16(&sK[buf^1][r*PLDH + col], &Kh[(size_t)(kt+r)*CH + col]);
                cp16(&sV[buf^1][r*PLDH + col], &Vh[(size_t)(kt+r)*CH + col]);
            }
            cp_commit();
        }

        wmma::fragment<wmma::accumulator,16,16,16,float> s[2][2];
        #pragma unroll
        for (int i=0;i<2;i++)
            #pragma unroll
            for (int j=0;j<2;j++) wmma::fill_fragment(s[i][j], 0.f);
        #pragma unroll
        for (int kk=0; kk<64; kk+=16) {
            wmma::fragment<wmma::matrix_a,16,16,16,__half,wmma::row_major> a[2];
            wmma::fragment<wmma::matrix_b,16,16,16,__half,wmma::col_major> bf[2];
            #pragma unroll
            for (int i=0;i<2;i++)
                wmma::load_matrix_sync(a[i], &sQ[(wr*32+i*16)*PLDH + kk], PLDH);
            #pragma unroll
            for (int j=0;j<2;j++)
                wmma::load_matrix_sync(bf[j], &sK[buf][(wc*32+j*16)*PLDH + kk], PLDH);
            #pragma unroll
            for (int i=0;i<2;i++)
                #pragma unroll
                for (int j=0;j<2;j++)
                    wmma::mma_sync(s[i][j], a[i], bf[j], s[i][j]);
        }

        #pragma unroll
        for (int i=0;i<2;i++)
            #pragma unroll
            for (int j=0;j<2;j++) {
                wmma::fragment<wmma::accumulator,16,16,16,__half> hp;
                #pragma unroll
                for (int t=0;t<hp.num_elements;t++)
                    hp.x[t] = __float2half_rn(__expf(s[i][j].x[t] * 0.125f));
                wmma::store_matrix_sync(&sP[(wr*32+i*16)*PLDH + wc*32 + j*16], hp,
                                        PLDH, wmma::mem_row_major);
            }
        __syncthreads();

        {
            const __half* bp = &sP[myrow*PLDH + cb];
            #pragma unroll
            for (int t=0;t<16;t++) {
                float2 p2 = __half22float2(*(const __half2*)&bp[t*2]);
                l += p2.x + p2.y;
            }
        }

        #pragma unroll
        for (int kk=0; kk<64; kk+=16) {
            wmma::fragment<wmma::matrix_a,16,16,16,__half,wmma::row_major> pa[2];
            wmma::fragment<wmma::matrix_b,16,16,16,__half,wmma::row_major> vb[2];
            #pragma unroll
            for (int i=0;i<2;i++)
                wmma::load_matrix_sync(pa[i], &sP[(wr*32+i*16)*PLDH + kk], PLDH);
            #pragma unroll
            for (int j=0;j<2;j++)
                wmma::load_matrix_sync(vb[j], &sV[buf][kk*PLDH + wc*32 + j*16], PLDH);
            #pragma unroll
            for (int i=0;i<2;i++)
                #pragma unroll
                for (int j=0;j<2;j++)
                    wmma::mma_sync(o[i][j], pa[i], vb[j], o[i][j]);
        }
    }

    l += __shfl_xor_sync(0xffffffffu, l, 1);
    if ((tid & 1) == 0) sL[myrow] = 1.f / l;
    __syncthreads();

    #pragma unroll
    for (int i=0;i<2;i++)
        #pragma unroll
        for (int j=0;j<2;j++)
            wmma::store_matrix_sync(&sO[(wr*32+i*16)*68 + wc*32 + j*16], o[i][j],
                                    68, wmma::mem_row_major);
    __syncthreads();

    #pragma unroll
    for (int t=0;t<32;t++) {
        int idx = tid + (t<<8);
        int r = idx >> 6, cc = idx & 63;
        g_attnh[(size_t)(b*SEQ + q0 + r)*CH + h*HDIM + cc] =
            __float2half_rn(sO[r*68+cc] * sL[r]);
    }
}

// =====================================================================
// Fused residual + LayerNorm, float4-vectorized.
// Residual source: external fp32 (Rext) or fp16 scratch (ridh).
// Outputs: optional fp32 (Oext/oidf) and/or fp16 (oidh).
// =====================================================================
__global__ __launch_bounds__(256)
void ln_kernel(int aidf, const float* __restrict__ Rext, int ridh,
               const float* __restrict__ g, const float* __restrict__ bb,
               float* __restrict__ Oext, int oidf, int oidh)
{
    const float* A = scratch_f(aidf);
    const __half* Rh = (ridh > 0) ? scratch_h(ridh) : nullptr;
    float* out = Oext ? Oext : scratch_f(oidf);
    __half* outh = (oidh > 0) ? scratch_h(oidh) : nullptr;

    __shared__ float s1[8], s2[8];
    const int row = blockIdx.x;
    const size_t base = (size_t)row * CH;
    const int tid = threadIdx.x;

    float4 a4 = ((const float4*)(A + base))[tid];
    float r0, r1, r2, r3;
    if (Rh) {
        __half2 h0 = ((const __half2*)(Rh + base))[tid*2];
        __half2 h1 = ((const __half2*)(Rh + base))[tid*2+1];
        float2 f0 = __half22float2(h0), f1 = __half22float2(h1);
        r0 = f0.x; r1 = f0.y; r2 = f1.x; r3 = f1.y;
    } else {
        float4 r4 = ((const float4*)(Rext + base))[tid];
        r0 = r4.x; r1 = r4.y; r2 = r4.z; r3 = r4.w;
    }
    float v0 = a4.x + r0, v1 = a4.y + r1, v2 = a4.z + r2, v3 = a4.w + r3;
    float sum = v0 + v1 + v2 + v3;
    float sq  = v0*v0 + v1*v1 + v2*v2 + v3*v3;

    #pragma unroll
    for (int o=16;o;o>>=1) {
        sum += __shfl_xor_sync(0xffffffffu, sum, o);
        sq  += __shfl_xor_sync(0xffffffffu, sq,  o);
    }
    if ((tid & 31) == 0) { s1[tid>>5] = sum; s2[tid>>5] = sq; }
    __syncthreads();
    if (tid < 32) {
        float a = (tid < 8) ? s1[tid] : 0.f;
        float b2 = (tid < 8) ? s2[tid] : 0.f;
        #pragma unroll
        for (int o=4;o;o>>=1) {
            a  += __shfl_xor_sync(0xffffffffu, a,  o);
            b2 += __shfl_xor_sync(0xffffffffu, b2, o);
        }
        if (tid == 0) { s1[0] = a; s2[0] = b2; }
    }
    __syncthreads();
    float mean = s1[0] * (1.f/CH);
    float var  = s2[0] * (1.f/CH) - mean*mean;
    float rstd = rsqrtf(var + 1e-5f);

    float4 g4 = ((const float4*)g)[tid];
    float4 b4 = ((const float4*)bb)[tid];
    float4 o4;
    o4.x = (v0 - mean) * rstd * g4.x + b4.x;
    o4.y = (v1 - mean) * rstd * g4.y + b4.y;
    o4.z = (v2 - mean) * rstd * g4.z + b4.z;
    o4.w = (v3 - mean) * rstd * g4.w + b4.w;
    if (out) ((float4*)(out + base))[tid] = o4;
    if (outh) {
        __half2* oh2 = (__half2*)(outh + base);
        oh2[tid*2]   = __floats2half2_rn(o4.x, o4.y);
        oh2[tid*2+1] = __floats2half2_rn(o4.z, o4.w);
    }
}

// =====================================================================
extern "C" void kernel_launch(void* const* d_in, const int* in_sizes, int n_in,
                              void* d_out, int out_size)
{
    const float *x, *keys, *Wq, *Wk, *Wv, *Wo, *ln1_g, *ln1_b;
    const float *fc1_w, *fc1_b, *fc2_w, *fc2_b, *ln2_g, *ln2_b;

    if (in_sizes[0] == MROWS*CH) {
        x     = (const float*)d_in[0];
        keys  = (const float*)d_in[1];
        Wq    = (const float*)d_in[2];
        Wk    = (const float*)d_in[3];
        Wv    = (const float*)d_in[4];
        Wo    = (const float*)d_in[5];
        ln1_g = (const float*)d_in[6];
        ln1_b = (const float*)d_in[7];
        fc1_w = (const float*)d_in[8];
        fc1_b = (const float*)d_in[9];
        fc2_w = (const float*)d_in[10];
        fc2_b = (const float*)d_in[11];
        ln2_g = (const float*)d_in[12];
        ln2_b = (const float*)d_in[13];
    } else {
        Wk    = (const float*)d_in[0];
        Wo    = (const float*)d_in[1];
        Wq    = (const float*)d_in[2];
        Wv    = (const float*)d_in[3];
        fc1_b = (const float*)d_in[4];
        fc1_w = (const float*)d_in[5];
        fc2_b = (const float*)d_in[6];
        fc2_w = (const float*)d_in[7];
        keys  = (const float*)d_in[8];
        ln1_b = (const float*)d_in[9];
        ln1_g = (const float*)d_in[10];
        ln2_b = (const float*)d_in[11];
        ln2_g = (const float*)d_in[12];
        x     = (const float*)d_in[13];
    }
    float* out = (float*)d_out;

    const int GEMM_SMEM  = 27648 * (int)sizeof(__half);            // 55296 B (qkv)
    const int GEMMB_SMEM = 27648 * (int)sizeof(__half) + 4352;     // 59648 B (+bias tile)
    const int ATTN_SMEM  = 36864 * (int)sizeof(__half) + 512;      // 74240 B
    cudaFuncSetAttribute(gemm_qkv,    cudaFuncAttributeMaxDynamicSharedMemorySize, GEMM_SMEM);
    cudaFuncSetAttribute(gemm_h<0,0>, cudaFuncAttributeMaxDynamicSharedMemorySize, GEMM_SMEM);
    cudaFuncSetAttribute(gemm_h<2,1>, cudaFuncAttributeMaxDynamicSharedMemorySize, GEMMB_SMEM);
    cudaFuncSetAttribute(gemm_h<1,0>, cudaFuncAttributeMaxDynamicSharedMemorySize, GEMMB_SMEM);
    cudaFuncSetAttribute(attn_kernel, cudaFuncAttributeMaxDynamicSharedMemorySize, ATTN_SMEM);

    dim3 blk(256);
    dim3 gQKV(CH/64, MROWS/128, 3);   // (16, 64, 3)
    dim3 g1024(CH/64, MROWS/128);     // (16, 64)
    dim3 g2048(FF/64, MROWS/128);     // (32, 64)

    // 0) fp32 -> fp16 conversion of inputs + weights
    conv8<<<2048, blk>>>(x, keys, Wq, Wk, Wv, Wo, fc1_w, fc2_w);

    // 1) QKV projections, one launch
    gemm_qkv<<<gQKV, blk, GEMM_SMEM>>>();

    // 2) attention: fp16 Q/K/V -> fp16 attnh
    dim3 ga(SEQ/128, BATCH*NHEAD);
    attn_kernel<<<ga, blk, ATTN_SMEM>>>();

    // 3) output projection (direct fp32 store) + residual LN1 (fp16 out only)
    gemm_h<0,0><<<g1024, blk, GEMM_SMEM>>>(12, 6, nullptr, 1, MROWS, CH, CH);  // g_O
    ln_kernel<<<MROWS, blk>>>(1, x, 0, ln1_g, ln1_b, nullptr, 0, 13);          // g_inth only

    // 4) MLP (register epilogues)
    gemm_h<2,1><<<g2048, blk, GEMMB_SMEM>>>(13, 7, fc1_b, 14, MROWS, FF, CH);  // H1h
    gemm_h<1,0><<<g1024, blk, GEMMB_SMEM>>>(14, 8, fc2_b, 3,  MROWS, CH, FF);  // g_F
    ln_kernel<<<MROWS, blk>>>(3, nullptr, 13, ln2_g, ln2_b, out, 0, 0);        // residual fp16
}